// round 1
// baseline (speedup 1.0000x reference)
#include <cuda_runtime.h>

// Problem constants
#define A_DIM 2048
#define D_DIM 128
#define O_DIM 128
#define F_DIM 16
#define KBIG  (A_DIM * F_DIM)   // 32768  (k = b*F + f, contiguous in conn)
#define FILT_ROW 2080           // F_DIM * (D_DIM + 2)
#define NSPLIT 32
#define KC (KBIG / NSPLIT)      // 1024

// Scratch (allocation-free rule: __device__ globals)
__device__ float g_W[KBIG * O_DIM];                  // 16 MB: W[(b*F+f)*128 + o]
__device__ float g_part[NSPLIT * A_DIM * O_DIM];     // 32 MB: split-K partials

// ---------------------------------------------------------------------------
// Kernel 1: W[b,f,o] = sum_d node[b,d] * filt[o,f,d]
// 16 independent 2048x128x128 GEMMs (one per f). Tile: 64(M) x 128(N) x 16(K).
// ---------------------------------------------------------------------------
__global__ __launch_bounds__(256) void k_build_w(const float* __restrict__ node,
                                                 const float* __restrict__ filt) {
    __shared__ float As[64][16];    // node tile [m][k]
    __shared__ float Bs[16][128];   // filt tile [k][o]

    const int b0 = blockIdx.x * 64;
    const int f  = blockIdx.y;
    const int t  = threadIdx.x;
    const int r  = t >> 5;          // 0..7  -> 8 rows of m each
    const int c  = t & 31;          // 0..31 -> 4 cols of o each

    float acc[8][4];
    #pragma unroll
    for (int i = 0; i < 8; i++)
        #pragma unroll
        for (int j = 0; j < 4; j++) acc[i][j] = 0.f;

    for (int k0 = 0; k0 < D_DIM; k0 += 16) {
        // Load A: 64x16 floats (float4 per thread)
        {
            const int m  = t >> 2;
            const int kq = (t & 3) * 4;
            const float4 v = *reinterpret_cast<const float4*>(
                &node[(b0 + m) * D_DIM + k0 + kq]);
            As[m][kq + 0] = v.x; As[m][kq + 1] = v.y;
            As[m][kq + 2] = v.z; As[m][kq + 3] = v.w;
        }
        // Load B: filt[o, f, k0..k0+15] -> Bs[k][o]  (16x128 floats, 8 per thread)
        {
            const int o  = t & 127;
            const int kh = (t >> 7) * 8;
            const float* src = &filt[o * FILT_ROW + f * 130 + k0 + kh];
            #pragma unroll
            for (int j = 0; j < 8; j++) Bs[kh + j][o] = src[j];
        }
        __syncthreads();

        #pragma unroll
        for (int k = 0; k < 16; k++) {
            float a[8], bb[4];
            #pragma unroll
            for (int i = 0; i < 8; i++) a[i] = As[r * 8 + i][k];
            #pragma unroll
            for (int j = 0; j < 4; j++) bb[j] = Bs[k][c * 4 + j];
            #pragma unroll
            for (int i = 0; i < 8; i++)
                #pragma unroll
                for (int j = 0; j < 4; j++)
                    acc[i][j] += a[i] * bb[j];
        }
        __syncthreads();
    }

    #pragma unroll
    for (int i = 0; i < 8; i++) {
        const int b = b0 + r * 8 + i;
        #pragma unroll
        for (int j = 0; j < 4; j++)
            g_W[(b * F_DIM + f) * O_DIM + c * 4 + j] = acc[i][j];
    }
}

// ---------------------------------------------------------------------------
// Kernel 2: big GEMM  part[s][a,o] = sum_{k in split s} conn2d[a,k] * W[k,o]
// M=2048, N=128, K=32768 split 32 ways. Tile: 128x128x8, 256 threads, 8x8/thread.
// ---------------------------------------------------------------------------
__global__ __launch_bounds__(256) void k_big_gemm(const float* __restrict__ conn) {
    __shared__ float As[8][128];    // conn tile, stored transposed [k][m]
    __shared__ float Bs[8][128];    // W tile [k][n]

    const int m0    = blockIdx.x * 128;
    const int kbase = blockIdx.y * KC;
    const int t  = threadIdx.x;
    const int tx = t & 15;          // n group: 8 cols
    const int ty = t >> 4;          // m group: 8 rows

    float acc[8][8];
    #pragma unroll
    for (int i = 0; i < 8; i++)
        #pragma unroll
        for (int j = 0; j < 8; j++) acc[i][j] = 0.f;

    for (int k0 = 0; k0 < KC; k0 += 8) {
        // A tile: 128 rows x 8 k (float4 per thread), transpose into As[k][m]
        {
            const int m  = t >> 1;
            const int kq = (t & 1) * 4;
            const float4 v = *reinterpret_cast<const float4*>(
                &conn[(size_t)(m0 + m) * KBIG + kbase + k0 + kq]);
            As[kq + 0][m] = v.x; As[kq + 1][m] = v.y;
            As[kq + 2][m] = v.z; As[kq + 3][m] = v.w;
        }
        // B tile: 8 k x 128 n (float4 per thread)
        {
            const int k = t >> 5;
            const int n = (t & 31) * 4;
            *reinterpret_cast<float4*>(&Bs[k][n]) =
                *reinterpret_cast<const float4*>(&g_W[(size_t)(kbase + k0 + k) * O_DIM + n]);
        }
        __syncthreads();

        #pragma unroll
        for (int k = 0; k < 8; k++) {
            float a[8], b[8];
            #pragma unroll
            for (int i = 0; i < 8; i++) a[i] = As[k][ty * 8 + i];
            #pragma unroll
            for (int j = 0; j < 8; j++) b[j] = Bs[k][tx * 8 + j];
            #pragma unroll
            for (int i = 0; i < 8; i++)
                #pragma unroll
                for (int j = 0; j < 8; j++)
                    acc[i][j] += a[i] * b[j];
        }
        __syncthreads();
    }

    float* dst = &g_part[(size_t)blockIdx.y * (A_DIM * O_DIM)];
    #pragma unroll
    for (int i = 0; i < 8; i++) {
        const int row = m0 + ty * 8 + i;
        #pragma unroll
        for (int j = 0; j < 8; j++)
            dst[row * O_DIM + tx * 8 + j] = acc[i][j];
    }
}

// ---------------------------------------------------------------------------
// Kernel 3: out[a,o] = sum_s part[s][a,o] + sum_f sum_j bond[a,f,j]*filt[o,f,128+j]
// Deterministic fixed-order reduction (no float atomics).
// ---------------------------------------------------------------------------
__global__ __launch_bounds__(256) void k_reduce(const float* __restrict__ bond,
                                                const float* __restrict__ filt,
                                                float* __restrict__ out) {
    const int idx = blockIdx.x * 256 + threadIdx.x;   // a*128 + o
    const int a = idx >> 7;
    const int o = idx & 127;

    float s = 0.f;
    #pragma unroll
    for (int sp = 0; sp < NSPLIT; sp++)
        s += g_part[(size_t)sp * (A_DIM * O_DIM) + idx];

    #pragma unroll
    for (int f = 0; f < F_DIM; f++) {
        s += bond[a * (F_DIM * 2) + 2 * f + 0] * filt[o * FILT_ROW + f * 130 + 128];
        s += bond[a * (F_DIM * 2) + 2 * f + 1] * filt[o * FILT_ROW + f * 130 + 129];
    }
    out[idx] = s;
}

// ---------------------------------------------------------------------------
extern "C" void kernel_launch(void* const* d_in, const int* in_sizes, int n_in,
                              void* d_out, int out_size) {
    const float* node = (const float*)d_in[0];   // (2048, 128)
    const float* conn = (const float*)d_in[1];   // (2048, 2048, 16)
    const float* bond = (const float*)d_in[2];   // (2048, 16, 2)
    const float* filt = (const float*)d_in[3];   // (128, 16, 130)
    float* out = (float*)d_out;                  // (2048, 128)

    (void)in_sizes; (void)n_in; (void)out_size;

    k_build_w<<<dim3(A_DIM / 64, F_DIM), 256>>>(node, filt);
    k_big_gemm<<<dim3(A_DIM / 128, NSPLIT), 256>>>(conn);
    k_reduce<<<(A_DIM * O_DIM) / 256, 256>>>(bond, filt, out);
}

// round 3
// speedup vs baseline: 2.8066x; 2.8066x over previous
#include <cuda_runtime.h>
#include <cstdint>

// ---------------------------------------------------------------- constants
#define A_DIM    2048
#define D_DIM    128
#define O_DIM    128
#define F_DIM    16
#define KBIG     (A_DIM * F_DIM)      // 32768; k = b*16 + f (contiguous in conn)
#define FILT_ROW 2080                 // 16 * 130
#define KSPLIT   8
#define KC       (KBIG / KSPLIT)      // 4096
#define KT       32                   // k-depth per tile
#define STAGES   4

// k_big smem: As[128][36] + Bs[32][132] per stage (floats)
#define BIG_A_F   (128 * 36)          // 4608
#define BIG_B_F   (32 * 132)          // 4224
#define BIG_ST_F  (BIG_A_F + BIG_B_F) // 8832
#define BIG_SMEM  (STAGES * BIG_ST_F * 4)   // 141312 B

// k_wbuild smem: As[128][36] + Bs[128][36] per stage
#define WB_A_F    (128 * 36)
#define WB_ST_F   (2 * WB_A_F)        // 9216
#define WB_SMEM   (STAGES * WB_ST_F * 4)    // 147456 B

// scratch (__device__ globals: allocation-free rule)
__device__ float g_W[(size_t)KBIG * O_DIM];                  // W[k][o], 16 MB
__device__ float g_part[(size_t)KSPLIT * A_DIM * O_DIM];     // 8 MB

// ---------------------------------------------------------------- utils
__device__ __forceinline__ uint32_t f2tf(float x) {
    uint32_t u;
    asm("cvt.rna.tf32.f32 %0, %1;" : "=r"(u) : "f"(x));
    return u;
}
__device__ __forceinline__ void mma8(float* d, const uint32_t* a, const uint32_t* b) {
    asm volatile(
        "mma.sync.aligned.m16n8k8.row.col.f32.tf32.tf32.f32 "
        "{%0,%1,%2,%3}, {%4,%5,%6,%7}, {%8,%9}, {%0,%1,%2,%3};"
        : "+f"(d[0]), "+f"(d[1]), "+f"(d[2]), "+f"(d[3])
        : "r"(a[0]), "r"(a[1]), "r"(a[2]), "r"(a[3]), "r"(b[0]), "r"(b[1]));
}
__device__ __forceinline__ void cpa16(void* dst, const void* src) {
    uint32_t d = (uint32_t)__cvta_generic_to_shared(dst);
    asm volatile("cp.async.cg.shared.global [%0], [%1], 16;" :: "r"(d), "l"(src));
}
__device__ __forceinline__ void cpa8(void* dst, const void* src) {
    uint32_t d = (uint32_t)__cvta_generic_to_shared(dst);
    asm volatile("cp.async.ca.shared.global [%0], [%1], 8;" :: "r"(d), "l"(src));
}
__device__ __forceinline__ void cp_commit() { asm volatile("cp.async.commit_group;"); }
__device__ __forceinline__ void cp_wait2()  { asm volatile("cp.async.wait_group 2;"); }

// ---------------------------------------------------------------------------
// Kernel 1: W[k = b*16+f][o] = sum_d filt[o,f,d] * node[b,d]
// grid = (16 b-tiles, 16 f). GEMM: M=o=128, N=b=128, K=d=128.
// Epilogue transposes D[o][b] through smem so g_W rows (contiguous o) are
// written coalesced.
// ---------------------------------------------------------------------------
__global__ void __launch_bounds__(256, 1) k_wbuild(const float* __restrict__ node,
                                                   const float* __restrict__ filt) {
    extern __shared__ float smf[];
    const int t = threadIdx.x, wid = t >> 5, lane = t & 31;
    const int wm = wid >> 1, wn = wid & 1;     // warp grid 4(M) x 2(N)
    const int b0 = blockIdx.x * 128;
    const int f  = blockIdx.y;
    const int ITERS = D_DIM / KT;              // 4

    float acc[2][8][4];
    #pragma unroll
    for (int i = 0; i < 2; i++)
        #pragma unroll
        for (int j = 0; j < 8; j++)
            #pragma unroll
            for (int q = 0; q < 4; q++) acc[i][j][q] = 0.f;

    auto load_tiles = [&](int it, int s) {
        float* As = smf + s * WB_ST_F;
        float* Bs = As + WB_A_F;
        const int d0 = it * KT;
        // A = filt[o, f, d0..d0+31]  (8B chunks: f*130 is only 8B-aligned)
        #pragma unroll
        for (int i = 0; i < 8; i++) {
            int c = t + 256 * i;               // 0..2047
            int o = c >> 4, h = c & 15;
            cpa8(As + o * 36 + h * 2,
                 filt + (size_t)o * FILT_ROW + f * 130 + d0 + h * 2);
        }
        // B = node[b0+n, d0..d0+31]  (float4)
        #pragma unroll
        for (int i = 0; i < 4; i++) {
            int c = t + 256 * i;               // 0..1023
            int n = c >> 3, j = c & 7;
            cpa16(Bs + n * 36 + j * 4,
                  node + (size_t)(b0 + n) * D_DIM + d0 + j * 4);
        }
    };

    #pragma unroll
    for (int p = 0; p < STAGES - 1; p++) {
        if (p < ITERS) load_tiles(p, p);
        cp_commit();
    }

    for (int it = 0; it < ITERS; ++it) {
        cp_wait2();
        __syncthreads();
        if (it + 3 < ITERS) load_tiles(it + 3, (it + 3) & 3);
        cp_commit();

        const float* As = smf + (it & 3) * WB_ST_F;
        const float* Bs = As + WB_A_F;
        #pragma unroll
        for (int kc = 0; kc < 4; kc++) {
            uint32_t a[2][4], b[8][2];
            #pragma unroll
            for (int i = 0; i < 2; i++) {
                const float* ap = As + (wm * 32 + i * 16 + (lane >> 2)) * 36
                                     + kc * 8 + (lane & 3);
                a[i][0] = f2tf(ap[0]);       a[i][1] = f2tf(ap[8 * 36]);
                a[i][2] = f2tf(ap[4]);       a[i][3] = f2tf(ap[8 * 36 + 4]);
            }
            #pragma unroll
            for (int j = 0; j < 8; j++) {
                const float* bp = Bs + (wn * 64 + j * 8 + (lane >> 2)) * 36
                                     + kc * 8 + (lane & 3);
                b[j][0] = f2tf(bp[0]);       b[j][1] = f2tf(bp[4]);
            }
            #pragma unroll
            for (int i = 0; i < 2; i++)
                #pragma unroll
                for (int j = 0; j < 8; j++) mma8(acc[i][j], a[i], b[j]);
        }
    }

    // transpose D[m=o][n=b] -> tile[n][o] in smem, then coalesced rows out
    __syncthreads();
    float* tile = smf;                          // 128 x 132 floats
    #pragma unroll
    for (int i = 0; i < 2; i++)
        #pragma unroll
        for (int j = 0; j < 8; j++) {
            const int m = wm * 32 + i * 16 + (lane >> 2);
            const int n = wn * 64 + j * 8 + (lane & 3) * 2;
            tile[n * 132 + m]             = acc[i][j][0];
            tile[(n + 1) * 132 + m]       = acc[i][j][1];
            tile[n * 132 + m + 8]         = acc[i][j][2];
            tile[(n + 1) * 132 + m + 8]   = acc[i][j][3];
        }
    __syncthreads();
    {
        const int n = t >> 1, half = t & 1;
        const float* src = tile + n * 132 + half * 64;
        float* dst = g_W + ((size_t)(b0 + n) * F_DIM + f) * O_DIM + half * 64;
        #pragma unroll
        for (int q = 0; q < 16; q++)
            *reinterpret_cast<float4*>(dst + q * 4) =
                *reinterpret_cast<const float4*>(src + q * 4);
    }
}

// ---------------------------------------------------------------------------
// Kernel 2: part[s][a,o] = sum_{k in split s} conn2d[a,k] * W[k,o]
// grid = (16 m-tiles, KSPLIT). GEMM: M=128, N=128, K=4096 (128 ktiles of 32).
// ---------------------------------------------------------------------------
__global__ void __launch_bounds__(256, 1) k_big(const float* __restrict__ conn) {
    extern __shared__ float smf[];
    const int t = threadIdx.x, wid = t >> 5, lane = t & 31;
    const int wm = wid >> 1, wn = wid & 1;
    const int m0    = blockIdx.x * 128;
    const int kbase = blockIdx.y * KC;
    const int ITERS = KC / KT;                 // 128

    float acc[2][8][4];
    #pragma unroll
    for (int i = 0; i < 2; i++)
        #pragma unroll
        for (int j = 0; j < 8; j++)
            #pragma unroll
            for (int q = 0; q < 4; q++) acc[i][j][q] = 0.f;

    auto load_tiles = [&](int it, int s) {
        float* As = smf + s * BIG_ST_F;        // [128][36]
        float* Bs = As + BIG_A_F;              // [32][132]
        const int kof = kbase + it * KT;
        #pragma unroll
        for (int i = 0; i < 4; i++) {
            int c = t + 256 * i;               // 0..1023
            int m = c >> 3, j = c & 7;
            cpa16(As + m * 36 + j * 4,
                  conn + (size_t)(m0 + m) * KBIG + kof + j * 4);
        }
        #pragma unroll
        for (int i = 0; i < 4; i++) {
            int c = t + 256 * i;               // 0..1023
            int k = c >> 5, j = c & 31;
            cpa16(Bs + k * 132 + j * 4,
                  g_W + (size_t)(kof + k) * O_DIM + j * 4);
        }
    };

    #pragma unroll
    for (int p = 0; p < STAGES - 1; p++) {
        load_tiles(p, p);
        cp_commit();
    }

    for (int it = 0; it < ITERS; ++it) {
        cp_wait2();
        __syncthreads();
        if (it + 3 < ITERS) load_tiles(it + 3, (it + 3) & 3);
        cp_commit();

        const float* As = smf + (it & 3) * BIG_ST_F;
        const float* Bs = As + BIG_A_F;
        #pragma unroll
        for (int kc = 0; kc < 4; kc++) {
            uint32_t a[2][4], b[8][2];
            #pragma unroll
            for (int i = 0; i < 2; i++) {
                const float* ap = As + (wm * 32 + i * 16 + (lane >> 2)) * 36
                                     + kc * 8 + (lane & 3);
                a[i][0] = f2tf(ap[0]);       a[i][1] = f2tf(ap[8 * 36]);
                a[i][2] = f2tf(ap[4]);       a[i][3] = f2tf(ap[8 * 36 + 4]);
            }
            #pragma unroll
            for (int j = 0; j < 8; j++) {
                const float* bp = Bs + (kc * 8 + (lane & 3)) * 132
                                     + wn * 64 + j * 8 + (lane >> 2);
                b[j][0] = f2tf(bp[0]);       b[j][1] = f2tf(bp[4 * 132]);
            }
            #pragma unroll
            for (int i = 0; i < 2; i++)
                #pragma unroll
                for (int j = 0; j < 8; j++) mma8(acc[i][j], a[i], b[j]);
        }
    }

    float* dst = g_part + (size_t)blockIdx.y * (A_DIM * O_DIM);
    #pragma unroll
    for (int i = 0; i < 2; i++)
        #pragma unroll
        for (int j = 0; j < 8; j++) {
            const int r0  = m0 + wm * 32 + i * 16 + (lane >> 2);
            const int col = wn * 64 + j * 8 + (lane & 3) * 2;
            *reinterpret_cast<float2*>(dst + (size_t)r0 * O_DIM + col) =
                make_float2(acc[i][j][0], acc[i][j][1]);
            *reinterpret_cast<float2*>(dst + (size_t)(r0 + 8) * O_DIM + col) =
                make_float2(acc[i][j][2], acc[i][j][3]);
        }
}

// ---------------------------------------------------------------------------
// Kernel 3: out = sum_s part[s] + bond-term   (deterministic fp32)
// ---------------------------------------------------------------------------
__global__ void __launch_bounds__(256) k_reduce(const float* __restrict__ bond,
                                                const float* __restrict__ filt,
                                                float* __restrict__ out) {
    const int idx = blockIdx.x * 256 + threadIdx.x;   // a*128 + o
    const int a = idx >> 7;
    const int o = idx & 127;

    float s = 0.f;
    #pragma unroll
    for (int sp = 0; sp < KSPLIT; sp++)
        s += g_part[(size_t)sp * (A_DIM * O_DIM) + idx];

    #pragma unroll
    for (int f = 0; f < F_DIM; f++) {
        s += bond[a * (F_DIM * 2) + 2 * f + 0] * filt[o * FILT_ROW + f * 130 + 128];
        s += bond[a * (F_DIM * 2) + 2 * f + 1] * filt[o * FILT_ROW + f * 130 + 129];
    }
    out[idx] = s;
}

// ---------------------------------------------------------------------------
extern "C" void kernel_launch(void* const* d_in, const int* in_sizes, int n_in,
                              void* d_out, int out_size) {
    const float* node = (const float*)d_in[0];   // (2048, 128)
    const float* conn = (const float*)d_in[1];   // (2048, 2048, 16)
    const float* bond = (const float*)d_in[2];   // (2048, 16, 2)
    const float* filt = (const float*)d_in[3];   // (128, 16, 130)
    float* out = (float*)d_out;                  // (2048, 128)
    (void)in_sizes; (void)n_in; (void)out_size;

    cudaFuncSetAttribute(k_wbuild, cudaFuncAttributeMaxDynamicSharedMemorySize, WB_SMEM);
    cudaFuncSetAttribute(k_big,    cudaFuncAttributeMaxDynamicSharedMemorySize, BIG_SMEM);

    k_wbuild<<<dim3(A_DIM / 128, F_DIM), 256, WB_SMEM>>>(node, filt);
    k_big<<<dim3(A_DIM / 128, KSPLIT), 256, BIG_SMEM>>>(conn);
    k_reduce<<<(A_DIM * O_DIM) / 256, 256>>>(bond, filt, out);
}